// round 1
// baseline (speedup 1.0000x reference)
#include <cuda_runtime.h>
#include <cuda_bf16.h>
#include <cstdint>

#define NNODES 50000
#define NEDGES 800000
#define LN_EPS 1e-5f

// ---------------- scratch (static device globals; no runtime alloc) ----------
__device__ float g_h[NNODES * 128];     // GEMM output
__device__ float g_agg[NNODES * 128];   // aggregation buffer
__device__ float g_feat[NNODES * 128];  // LN output (next layer input)
__device__ float g_deg[NNODES];
__device__ float g_dinv[NNODES];
__device__ float g_norm[NEDGES];

// ---------------- f32x2 packed helpers --------------------------------------
__device__ __forceinline__ unsigned long long fma2(unsigned long long a,
                                                   unsigned long long b,
                                                   unsigned long long c) {
    unsigned long long d;
    asm("fma.rn.f32x2 %0, %1, %2, %3;" : "=l"(d) : "l"(a), "l"(b), "l"(c));
    return d;
}
__device__ __forceinline__ unsigned long long pack_dup(float v) {
    unsigned long long r;
    asm("mov.b64 %0, {%1, %1};" : "=l"(r) : "f"(v));
    return r;
}
__device__ __forceinline__ void unpack2(unsigned long long p, float& lo, float& hi) {
    asm("mov.b64 {%0, %1}, %2;" : "=f"(lo), "=f"(hi) : "l"(p));
}

// ---------------- precompute: degree / dinv / edge norm ----------------------
__global__ void deg_init_kernel() {
    int i = blockIdx.x * blockDim.x + threadIdx.x;
    if (i < NNODES) g_deg[i] = 1.0f;   // self-loop weight
}
__global__ void deg_acc_kernel(const int* __restrict__ dst, const float* __restrict__ w) {
    int e = blockIdx.x * blockDim.x + threadIdx.x;
    if (e < NEDGES) atomicAdd(&g_deg[dst[e]], w[e]);
}
__global__ void dinv_kernel() {
    int i = blockIdx.x * blockDim.x + threadIdx.x;
    if (i < NNODES) g_dinv[i] = rsqrtf(g_deg[i]);
}
__global__ void norm_kernel(const int* __restrict__ src, const int* __restrict__ dst,
                            const float* __restrict__ w) {
    int e = blockIdx.x * blockDim.x + threadIdx.x;
    if (e < NEDGES) g_norm[e] = g_dinv[src[e]] * w[e] * g_dinv[dst[e]];
}

// ---------------- GEMM: H = X[N,128] @ W[128,OUT] ----------------------------
// Block: 64 rows x OUT cols, 128 threads = 32 (col lanes) x 4 (row groups).
// Each thread: 16 rows as 8 f32x2 pairs, OUT/32 columns.
template <int OUT>
__global__ void gemm_kernel(const float* __restrict__ X, const float* __restrict__ W,
                            float* __restrict__ H) {
    constexpr int IN = 128;
    constexpr int NCOL = OUT / 32;
    __shared__ __align__(16) float xs[IN][66];   // transposed tile, even stride for 8B loads

    const int t = threadIdx.x;
    const int row0 = blockIdx.x * 64;

    for (int i = t; i < 64 * IN; i += 128) {
        int r = i >> 7, k = i & 127;
        int gr = row0 + r;
        xs[k][r] = (gr < NNODES) ? X[(size_t)gr * IN + k] : 0.0f;
    }
    __syncthreads();

    const int tx = t & 31;
    const int ty = t >> 5;

    unsigned long long acc[8][NCOL];
#pragma unroll
    for (int rp = 0; rp < 8; rp++)
#pragma unroll
        for (int j = 0; j < NCOL; j++) acc[rp][j] = 0ull;

#pragma unroll 2
    for (int k = 0; k < IN; k++) {
        unsigned long long w2[NCOL];
#pragma unroll
        for (int j = 0; j < NCOL; j++)
            w2[j] = pack_dup(W[(size_t)k * OUT + tx + 32 * j]);
#pragma unroll
        for (int rp = 0; rp < 8; rp++) {
            unsigned long long xv =
                *(const unsigned long long*)&xs[k][ty * 16 + 2 * rp];
#pragma unroll
            for (int j = 0; j < NCOL; j++) acc[rp][j] = fma2(xv, w2[j], acc[rp][j]);
        }
    }

#pragma unroll
    for (int rp = 0; rp < 8; rp++) {
        int r0 = row0 + ty * 16 + 2 * rp;
#pragma unroll
        for (int j = 0; j < NCOL; j++) {
            float lo, hi;
            unpack2(acc[rp][j], lo, hi);
            int c = tx + 32 * j;
            if (r0 < NNODES) H[(size_t)r0 * OUT + c] = lo;
            if (r0 + 1 < NNODES) H[(size_t)(r0 + 1) * OUT + c] = hi;
        }
    }
}

// ---------------- init: agg = dinv^2 * h + bias (self-loop + bias) -----------
template <int OUT>
__global__ void init_kernel(const float* __restrict__ H, const float* __restrict__ b,
                            float* __restrict__ Agg) {
    constexpr int Q = OUT / 4;
    int i = blockIdx.x * blockDim.x + threadIdx.x;
    if (i >= NNODES * Q) return;
    int node = i / Q;
    int cb = (i - node * Q) * 4;
    float di = g_dinv[node];
    float d2 = di * di;
    float4 h = *(const float4*)(H + (size_t)node * OUT + cb);
    float4 bv = *(const float4*)(b + cb);
    float4 o;
    o.x = d2 * h.x + bv.x;
    o.y = d2 * h.y + bv.y;
    o.z = d2 * h.z + bv.z;
    o.w = d2 * h.w + bv.w;
    *(float4*)(Agg + (size_t)node * OUT + cb) = o;
}

// ---------------- edge scatter: agg[dst] += norm * h[src] --------------------
template <int DIM>
__global__ void edge_kernel(const float* __restrict__ H, float* __restrict__ Agg,
                            const int* __restrict__ src, const int* __restrict__ dst) {
    int gt = blockIdx.x * blockDim.x + threadIdx.x;
    int e = gt >> 5;
    if (e >= NEDGES) return;
    int lane = gt & 31;
    int s = __ldg(&src[e]);
    int d = __ldg(&dst[e]);
    float nm = __ldg(&g_norm[e]);
    if (DIM == 128) {
        const float4 v = *(const float4*)(H + (size_t)s * 128 + lane * 4);
        float* p = Agg + (size_t)d * 128 + lane * 4;
        asm volatile("red.global.add.v4.f32 [%0], {%1, %2, %3, %4};" ::"l"(p),
                     "f"(v.x * nm), "f"(v.y * nm), "f"(v.z * nm), "f"(v.w * nm)
                     : "memory");
    } else {
        const float2 v = *(const float2*)(H + (size_t)s * 64 + lane * 2);
        float* p = Agg + (size_t)d * 64 + lane * 2;
        asm volatile("red.global.add.v2.f32 [%0], {%1, %2};" ::"l"(p),
                     "f"(v.x * nm), "f"(v.y * nm)
                     : "memory");
    }
}

// ---------------- LayerNorm (+ optional ReLU), warp per row ------------------
template <int DIM, bool RELU>
__global__ void ln_kernel(const float* __restrict__ A, const float* __restrict__ gm,
                          const float* __restrict__ bt, float* __restrict__ O) {
    int gt = blockIdx.x * blockDim.x + threadIdx.x;
    int r = gt >> 5;
    if (r >= NNODES) return;
    int lane = gt & 31;
    if (DIM == 128) {
        float4 v = *(const float4*)(A + (size_t)r * 128 + lane * 4);
        float s1 = v.x + v.y + v.z + v.w;
        float s2 = v.x * v.x + v.y * v.y + v.z * v.z + v.w * v.w;
#pragma unroll
        for (int o = 16; o > 0; o >>= 1) {
            s1 += __shfl_xor_sync(0xffffffffu, s1, o);
            s2 += __shfl_xor_sync(0xffffffffu, s2, o);
        }
        float mean = s1 * (1.0f / 128.0f);
        float var = s2 * (1.0f / 128.0f) - mean * mean;
        float inv = rsqrtf(var + LN_EPS);
        float4 gv = *(const float4*)(gm + lane * 4);
        float4 tv = *(const float4*)(bt + lane * 4);
        float4 o4;
        o4.x = (v.x - mean) * inv * gv.x + tv.x;
        o4.y = (v.y - mean) * inv * gv.y + tv.y;
        o4.z = (v.z - mean) * inv * gv.z + tv.z;
        o4.w = (v.w - mean) * inv * gv.w + tv.w;
        if (RELU) {
            o4.x = fmaxf(o4.x, 0.0f);
            o4.y = fmaxf(o4.y, 0.0f);
            o4.z = fmaxf(o4.z, 0.0f);
            o4.w = fmaxf(o4.w, 0.0f);
        }
        *(float4*)(O + (size_t)r * 128 + lane * 4) = o4;
    } else {
        float2 v = *(const float2*)(A + (size_t)r * 64 + lane * 2);
        float s1 = v.x + v.y;
        float s2 = v.x * v.x + v.y * v.y;
#pragma unroll
        for (int o = 16; o > 0; o >>= 1) {
            s1 += __shfl_xor_sync(0xffffffffu, s1, o);
            s2 += __shfl_xor_sync(0xffffffffu, s2, o);
        }
        float mean = s1 * (1.0f / 64.0f);
        float var = s2 * (1.0f / 64.0f) - mean * mean;
        float inv = rsqrtf(var + LN_EPS);
        float2 gv = *(const float2*)(gm + lane * 2);
        float2 tv = *(const float2*)(bt + lane * 2);
        float2 o2;
        o2.x = (v.x - mean) * inv * gv.x + tv.x;
        o2.y = (v.y - mean) * inv * gv.y + tv.y;
        if (RELU) {
            o2.x = fmaxf(o2.x, 0.0f);
            o2.y = fmaxf(o2.y, 0.0f);
        }
        *(float2*)(O + (size_t)r * 64 + lane * 2) = o2;
    }
}

// ---------------- host launch -------------------------------------------------
extern "C" void kernel_launch(void* const* d_in, const int* in_sizes, int n_in,
                              void* d_out, int out_size) {
    const float* x  = (const float*)d_in[0];
    const int*   ei = (const int*)d_in[1];
    const float* ew = (const float*)d_in[2];
    const float* W1 = (const float*)d_in[3];
    const float* b1 = (const float*)d_in[4];
    const float* g1 = (const float*)d_in[5];
    const float* t1 = (const float*)d_in[6];
    const float* W2 = (const float*)d_in[7];
    const float* b2 = (const float*)d_in[8];
    const float* g2 = (const float*)d_in[9];
    const float* t2 = (const float*)d_in[10];
    const float* W3 = (const float*)d_in[11];
    const float* b3 = (const float*)d_in[12];
    const float* g3 = (const float*)d_in[13];
    const float* t3 = (const float*)d_in[14];
    const int* src = ei;
    const int* dst = ei + NEDGES;
    float* out = (float*)d_out;

    float *h, *agg, *feat;
    cudaGetSymbolAddress((void**)&h, g_h);
    cudaGetSymbolAddress((void**)&agg, g_agg);
    cudaGetSymbolAddress((void**)&feat, g_feat);

    const int TB = 256;
    const int nblk_N = (NNODES + TB - 1) / TB;
    const int nblk_E = (NEDGES + TB - 1) / TB;
    const int nblk_edge = (NEDGES * 32 + TB - 1) / TB;   // warp per edge
    const int nblk_row = (NNODES * 32 + TB - 1) / TB;    // warp per row
    const int nblk_gemm = (NNODES + 63) / 64;

    // precompute deg / dinv / norm
    deg_init_kernel<<<nblk_N, TB>>>();
    deg_acc_kernel<<<nblk_E, TB>>>(dst, ew);
    dinv_kernel<<<nblk_N, TB>>>();
    norm_kernel<<<nblk_E, TB>>>(src, dst, ew);

    // layer 1
    gemm_kernel<128><<<nblk_gemm, 128>>>(x, W1, h);
    init_kernel<128><<<(NNODES * 32 + TB - 1) / TB, TB>>>(h, b1, agg);
    edge_kernel<128><<<nblk_edge, TB>>>(h, agg, src, dst);
    ln_kernel<128, true><<<nblk_row, TB>>>(agg, g1, t1, feat);

    // layer 2
    gemm_kernel<128><<<nblk_gemm, 128>>>(feat, W2, h);
    init_kernel<128><<<(NNODES * 32 + TB - 1) / TB, TB>>>(h, b2, agg);
    edge_kernel<128><<<nblk_edge, TB>>>(h, agg, src, dst);
    ln_kernel<128, true><<<nblk_row, TB>>>(agg, g2, t2, feat);

    // layer 3 (dout = 64, no relu), output straight to d_out
    gemm_kernel<64><<<nblk_gemm, 128>>>(feat, W3, h);
    init_kernel<64><<<(NNODES * 16 + TB - 1) / TB, TB>>>(h, b3, agg);
    edge_kernel<64><<<nblk_edge, TB>>>(h, agg, src, dst);
    ln_kernel<64, false><<<nblk_row, TB>>>(agg, g3, t3, out);
}

// round 2
// speedup vs baseline: 1.2814x; 1.2814x over previous
#include <cuda_runtime.h>
#include <cuda_bf16.h>
#include <cstdint>

#define NNODES 50000
#define NEDGES 800000
#define LN_EPS 1e-5f

// ---------------- scratch (static device globals; no runtime alloc) ----------
__device__ float g_h[NNODES * 128];     // GEMM output
__device__ float g_feat[NNODES * 128];  // LN output (next layer input)
__device__ float g_deg[NNODES];
__device__ float g_dinv[NNODES];
__device__ int   g_cnt[NNODES];         // in-degree counts
__device__ int   g_off[NNODES + 1];     // CSR offsets
__device__ int   g_cur[NNODES];         // fill cursors
__device__ int   g_csr_src[NEDGES];     // CSR: source node per slot
__device__ float g_csr_nrm[NEDGES];     // CSR: edge norm per slot

// ---------------- f32x2 packed helpers --------------------------------------
__device__ __forceinline__ unsigned long long fma2(unsigned long long a,
                                                   unsigned long long b,
                                                   unsigned long long c) {
    unsigned long long d;
    asm("fma.rn.f32x2 %0, %1, %2, %3;" : "=l"(d) : "l"(a), "l"(b), "l"(c));
    return d;
}
__device__ __forceinline__ unsigned long long pack_dup(float v) {
    unsigned long long r;
    asm("mov.b64 %0, {%1, %1};" : "=l"(r) : "f"(v));
    return r;
}
__device__ __forceinline__ void unpack2(unsigned long long p, float& lo, float& hi) {
    asm("mov.b64 {%0, %1}, %2;" : "=f"(lo), "=f"(hi) : "l"(p));
}

// ---------------- precompute ------------------------------------------------
__global__ void init_counts_kernel() {
    int i = blockIdx.x * blockDim.x + threadIdx.x;
    if (i < NNODES) {
        g_deg[i] = 1.0f;   // self-loop weight
        g_cnt[i] = 0;
    }
}

__global__ void count_kernel(const int* __restrict__ dst, const float* __restrict__ w) {
    int e = blockIdx.x * blockDim.x + threadIdx.x;
    if (e < NEDGES) {
        int d = dst[e];
        atomicAdd(&g_deg[d], w[e]);
        atomicAdd(&g_cnt[d], 1);
    }
}

__global__ void dinv_kernel() {
    int i = blockIdx.x * blockDim.x + threadIdx.x;
    if (i < NNODES) g_dinv[i] = rsqrtf(g_deg[i]);
}

// single-block exclusive scan over g_cnt -> g_off, init g_cur
__global__ void scan_kernel() {
    __shared__ int sums[1024];
    const int CHUNK = (NNODES + 1023) / 1024;   // 49
    int t = threadIdx.x;
    int base = t * CHUNK;
    int s = 0;
    for (int i = 0; i < CHUNK; i++) {
        int idx = base + i;
        if (idx < NNODES) s += g_cnt[idx];
    }
    sums[t] = s;
    __syncthreads();
    for (int off = 1; off < 1024; off <<= 1) {
        int v = sums[t];
        int u = (t >= off) ? sums[t - off] : 0;
        __syncthreads();
        sums[t] = v + u;
        __syncthreads();
    }
    int run = (t == 0) ? 0 : sums[t - 1];
    for (int i = 0; i < CHUNK; i++) {
        int idx = base + i;
        if (idx < NNODES) {
            g_off[idx] = run;
            g_cur[idx] = run;
            run += g_cnt[idx];
        }
    }
    if (t == 1023) g_off[NNODES] = run;   // == NEDGES
}

__global__ void fill_kernel(const int* __restrict__ src, const int* __restrict__ dst,
                            const float* __restrict__ w) {
    int e = blockIdx.x * blockDim.x + threadIdx.x;
    if (e >= NEDGES) return;
    int s = src[e];
    int d = dst[e];
    float nm = g_dinv[s] * w[e] * g_dinv[d];
    int pos = atomicAdd(&g_cur[d], 1);
    g_csr_src[pos] = s;
    g_csr_nrm[pos] = nm;
}

// ---------------- GEMM: H = X[N,128] @ W[128,OUT] ----------------------------
template <int OUT>
__global__ void gemm_kernel(const float* __restrict__ X, const float* __restrict__ W,
                            float* __restrict__ H) {
    constexpr int IN = 128;
    constexpr int NCOL = OUT / 32;
    __shared__ __align__(16) float xs[IN][66];

    const int t = threadIdx.x;
    const int row0 = blockIdx.x * 64;

    for (int i = t; i < 64 * IN; i += 128) {
        int r = i >> 7, k = i & 127;
        int gr = row0 + r;
        xs[k][r] = (gr < NNODES) ? X[(size_t)gr * IN + k] : 0.0f;
    }
    __syncthreads();

    const int tx = t & 31;
    const int ty = t >> 5;

    unsigned long long acc[8][NCOL];
#pragma unroll
    for (int rp = 0; rp < 8; rp++)
#pragma unroll
        for (int j = 0; j < NCOL; j++) acc[rp][j] = 0ull;

#pragma unroll 2
    for (int k = 0; k < IN; k++) {
        unsigned long long w2[NCOL];
#pragma unroll
        for (int j = 0; j < NCOL; j++)
            w2[j] = pack_dup(W[(size_t)k * OUT + tx + 32 * j]);
#pragma unroll
        for (int rp = 0; rp < 8; rp++) {
            unsigned long long xv =
                *(const unsigned long long*)&xs[k][ty * 16 + 2 * rp];
#pragma unroll
            for (int j = 0; j < NCOL; j++) acc[rp][j] = fma2(xv, w2[j], acc[rp][j]);
        }
    }

#pragma unroll
    for (int rp = 0; rp < 8; rp++) {
        int r0 = row0 + ty * 16 + 2 * rp;
#pragma unroll
        for (int j = 0; j < NCOL; j++) {
            float lo, hi;
            unpack2(acc[rp][j], lo, hi);
            int c = tx + 32 * j;
            if (r0 < NNODES) H[(size_t)r0 * OUT + c] = lo;
            if (r0 + 1 < NNODES) H[(size_t)(r0 + 1) * OUT + c] = hi;
        }
    }
}

// ------- fused: gather-aggregate (CSR) + self-loop + bias + LN (+ReLU) -------
// Warp per destination node.
template <int DIM, bool RELU>
__global__ void agg_ln_kernel(const float* __restrict__ H, const float* __restrict__ b,
                              const float* __restrict__ gm, const float* __restrict__ bt,
                              float* __restrict__ O) {
    int gt = blockIdx.x * blockDim.x + threadIdx.x;
    int node = gt >> 5;
    if (node >= NNODES) return;
    int lane = gt & 31;

    float di = g_dinv[node];
    float d2 = di * di;
    int beg = g_off[node];
    int end = g_off[node + 1];

    if (DIM == 128) {
        int c = lane * 4;
        float4 hv = *(const float4*)(H + (size_t)node * 128 + c);
        float4 bv = *(const float4*)(b + c);
        float4 acc;
        acc.x = d2 * hv.x + bv.x;
        acc.y = d2 * hv.y + bv.y;
        acc.z = d2 * hv.z + bv.z;
        acc.w = d2 * hv.w + bv.w;

        int j = beg;
        int s0 = 0; float nm0 = 0.0f;
        if (j < end) { s0 = __ldg(&g_csr_src[j]); nm0 = __ldg(&g_csr_nrm[j]); }
        while (j < end) {
            int s = s0; float nm = nm0;
            j++;
            if (j < end) { s0 = __ldg(&g_csr_src[j]); nm0 = __ldg(&g_csr_nrm[j]); }
            float4 v = *(const float4*)(H + (size_t)s * 128 + c);
            acc.x += nm * v.x;
            acc.y += nm * v.y;
            acc.z += nm * v.z;
            acc.w += nm * v.w;
        }

        float s1 = acc.x + acc.y + acc.z + acc.w;
        float s2 = acc.x * acc.x + acc.y * acc.y + acc.z * acc.z + acc.w * acc.w;
#pragma unroll
        for (int o = 16; o > 0; o >>= 1) {
            s1 += __shfl_xor_sync(0xffffffffu, s1, o);
            s2 += __shfl_xor_sync(0xffffffffu, s2, o);
        }
        float mean = s1 * (1.0f / 128.0f);
        float var = s2 * (1.0f / 128.0f) - mean * mean;
        float inv = rsqrtf(var + LN_EPS);
        float4 gv = *(const float4*)(gm + c);
        float4 tv = *(const float4*)(bt + c);
        float4 o4;
        o4.x = (acc.x - mean) * inv * gv.x + tv.x;
        o4.y = (acc.y - mean) * inv * gv.y + tv.y;
        o4.z = (acc.z - mean) * inv * gv.z + tv.z;
        o4.w = (acc.w - mean) * inv * gv.w + tv.w;
        if (RELU) {
            o4.x = fmaxf(o4.x, 0.0f);
            o4.y = fmaxf(o4.y, 0.0f);
            o4.z = fmaxf(o4.z, 0.0f);
            o4.w = fmaxf(o4.w, 0.0f);
        }
        *(float4*)(O + (size_t)node * 128 + c) = o4;
    } else {   // DIM == 64
        int c = lane * 2;
        float2 hv = *(const float2*)(H + (size_t)node * 64 + c);
        float2 bv = *(const float2*)(b + c);
        float2 acc;
        acc.x = d2 * hv.x + bv.x;
        acc.y = d2 * hv.y + bv.y;

        int j = beg;
        int s0 = 0; float nm0 = 0.0f;
        if (j < end) { s0 = __ldg(&g_csr_src[j]); nm0 = __ldg(&g_csr_nrm[j]); }
        while (j < end) {
            int s = s0; float nm = nm0;
            j++;
            if (j < end) { s0 = __ldg(&g_csr_src[j]); nm0 = __ldg(&g_csr_nrm[j]); }
            float2 v = *(const float2*)(H + (size_t)s * 64 + c);
            acc.x += nm * v.x;
            acc.y += nm * v.y;
        }

        float s1 = acc.x + acc.y;
        float s2 = acc.x * acc.x + acc.y * acc.y;
#pragma unroll
        for (int o = 16; o > 0; o >>= 1) {
            s1 += __shfl_xor_sync(0xffffffffu, s1, o);
            s2 += __shfl_xor_sync(0xffffffffu, s2, o);
        }
        float mean = s1 * (1.0f / 64.0f);
        float var = s2 * (1.0f / 64.0f) - mean * mean;
        float inv = rsqrtf(var + LN_EPS);
        float2 gv = *(const float2*)(gm + c);
        float2 tv = *(const float2*)(bt + c);
        float2 o2;
        o2.x = (acc.x - mean) * inv * gv.x + tv.x;
        o2.y = (acc.y - mean) * inv * gv.y + tv.y;
        if (RELU) {
            o2.x = fmaxf(o2.x, 0.0f);
            o2.y = fmaxf(o2.y, 0.0f);
        }
        *(float2*)(O + (size_t)node * 64 + c) = o2;
    }
}

// ---------------- host launch -------------------------------------------------
extern "C" void kernel_launch(void* const* d_in, const int* in_sizes, int n_in,
                              void* d_out, int out_size) {
    const float* x  = (const float*)d_in[0];
    const int*   ei = (const int*)d_in[1];
    const float* ew = (const float*)d_in[2];
    const float* W1 = (const float*)d_in[3];
    const float* b1 = (const float*)d_in[4];
    const float* g1 = (const float*)d_in[5];
    const float* t1 = (const float*)d_in[6];
    const float* W2 = (const float*)d_in[7];
    const float* b2 = (const float*)d_in[8];
    const float* g2 = (const float*)d_in[9];
    const float* t2 = (const float*)d_in[10];
    const float* W3 = (const float*)d_in[11];
    const float* b3 = (const float*)d_in[12];
    const float* g3 = (const float*)d_in[13];
    const float* t3 = (const float*)d_in[14];
    const int* src = ei;
    const int* dst = ei + NEDGES;
    float* out = (float*)d_out;

    float *h, *feat;
    cudaGetSymbolAddress((void**)&h, g_h);
    cudaGetSymbolAddress((void**)&feat, g_feat);

    const int TB = 256;
    const int nblk_N = (NNODES + TB - 1) / TB;
    const int nblk_E = (NEDGES + TB - 1) / TB;
    const int nblk_row = (NNODES * 32 + TB - 1) / TB;    // warp per node
    const int nblk_gemm = (NNODES + 63) / 64;

    // precompute: weighted degree + counts, dinv, CSR offsets, CSR fill
    init_counts_kernel<<<nblk_N, TB>>>();
    count_kernel<<<nblk_E, TB>>>(dst, ew);
    dinv_kernel<<<nblk_N, TB>>>();
    scan_kernel<<<1, 1024>>>();
    fill_kernel<<<nblk_E, TB>>>(src, dst, ew);

    // layer 1
    gemm_kernel<128><<<nblk_gemm, 128>>>(x, W1, h);
    agg_ln_kernel<128, true><<<nblk_row, TB>>>(h, b1, g1, t1, feat);

    // layer 2
    gemm_kernel<128><<<nblk_gemm, 128>>>(feat, W2, h);
    agg_ln_kernel<128, true><<<nblk_row, TB>>>(h, b2, g2, t2, feat);

    // layer 3 (dout = 64, no relu), output straight to d_out
    gemm_kernel<64><<<nblk_gemm, 128>>>(feat, W3, h);
    agg_ln_kernel<64, false><<<nblk_row, TB>>>(h, b3, g3, t3, out);
}

// round 3
// speedup vs baseline: 1.6195x; 1.2639x over previous
#include <cuda_runtime.h>
#include <cuda_bf16.h>
#include <cstdint>

#define NNODES 50000
#define NEDGES 800000
#define LN_EPS 1e-5f

#define SCAN_BS 512
#define SCAN_NB ((NNODES + SCAN_BS - 1) / SCAN_BS)   // 98

// ---------------- scratch (static device globals; no runtime alloc) ----------
__device__ float g_h[NNODES * 128];     // GEMM output
__device__ float g_feat[NNODES * 128];  // LN output (next layer input)
__device__ float g_deg[NNODES];
__device__ float g_dinv[NNODES];
__device__ int   g_cnt[NNODES];         // in-degree counts
__device__ int   g_off[NNODES + 1];     // CSR offsets
__device__ int   g_cur[NNODES];         // fill cursors
__device__ int   g_bsum[SCAN_NB];       // per-block totals
__device__ int   g_bpre[SCAN_NB];       // per-block exclusive prefix
__device__ int   g_csr_src[NEDGES];     // CSR: source node per slot
__device__ float g_csr_nrm[NEDGES];     // CSR: edge norm per slot

// ---------------- f32x2 packed helpers --------------------------------------
__device__ __forceinline__ unsigned long long fma2(unsigned long long a,
                                                   unsigned long long b,
                                                   unsigned long long c) {
    unsigned long long d;
    asm("fma.rn.f32x2 %0, %1, %2, %3;" : "=l"(d) : "l"(a), "l"(b), "l"(c));
    return d;
}
__device__ __forceinline__ unsigned long long pack_dup(float v) {
    unsigned long long r;
    asm("mov.b64 %0, {%1, %1};" : "=l"(r) : "f"(v));
    return r;
}
__device__ __forceinline__ void unpack2(unsigned long long p, float& lo, float& hi) {
    asm("mov.b64 {%0, %1}, %2;" : "=f"(lo), "=f"(hi) : "l"(p));
}

// ---------------- precompute ------------------------------------------------
__global__ void init_counts_kernel() {
    int i = blockIdx.x * blockDim.x + threadIdx.x;
    if (i < NNODES) {
        g_deg[i] = 1.0f;   // self-loop weight
        g_cnt[i] = 0;
    }
}

__global__ void count_kernel(const int* __restrict__ dst, const float* __restrict__ w) {
    int e = blockIdx.x * blockDim.x + threadIdx.x;
    if (e < NEDGES) {
        int d = dst[e];
        atomicAdd(&g_deg[d], w[e]);
        atomicAdd(&g_cnt[d], 1);
    }
}

// phase 1: per-block exclusive scan of g_cnt -> g_off (local), block total -> g_bsum
__global__ void scan_block_kernel() {
    __shared__ int wsum[SCAN_BS / 32];
    int t = threadIdx.x;
    int lane = t & 31;
    int wid = t >> 5;
    int i = blockIdx.x * SCAN_BS + t;
    int v = (i < NNODES) ? g_cnt[i] : 0;

    // warp inclusive scan
    int x = v;
#pragma unroll
    for (int o = 1; o < 32; o <<= 1) {
        int y = __shfl_up_sync(0xffffffffu, x, o);
        if (lane >= o) x += y;
    }
    if (lane == 31) wsum[wid] = x;
    __syncthreads();
    if (wid == 0) {
        int s = (lane < SCAN_BS / 32) ? wsum[lane] : 0;
#pragma unroll
        for (int o = 1; o < SCAN_BS / 32; o <<= 1) {
            int y = __shfl_up_sync(0xffffffffu, s, o);
            if (lane >= o) s += y;
        }
        if (lane < SCAN_BS / 32) wsum[lane] = s;   // inclusive warp sums
    }
    __syncthreads();
    int wpre = (wid == 0) ? 0 : wsum[wid - 1];
    int excl = wpre + x - v;
    if (i < NNODES) g_off[i] = excl;
    if (t == SCAN_BS - 1) g_bsum[blockIdx.x] = wpre + x;
}

// phase 2: single block scans the 98 block totals -> exclusive prefix
__global__ void scan_tops_kernel() {
    __shared__ int s[128];
    int t = threadIdx.x;
    s[t] = (t < SCAN_NB) ? g_bsum[t] : 0;
    __syncthreads();
#pragma unroll
    for (int o = 1; o < 128; o <<= 1) {
        int v = s[t];
        int u = (t >= o) ? s[t - o] : 0;
        __syncthreads();
        s[t] = v + u;
        __syncthreads();
    }
    if (t < SCAN_NB) g_bpre[t] = (t == 0) ? 0 : s[t - 1];
}

// phase 3: add block prefix, init cursors; fused dinv
__global__ void scan_add_kernel() {
    int i = blockIdx.x * SCAN_BS + threadIdx.x;
    if (i < NNODES) {
        int off = g_off[i] + g_bpre[blockIdx.x];
        g_off[i] = off;
        g_cur[i] = off;
        g_dinv[i] = rsqrtf(g_deg[i]);
    }
    if (i == 0) g_off[NNODES] = NEDGES;
}

__global__ void fill_kernel(const int* __restrict__ src, const int* __restrict__ dst,
                            const float* __restrict__ w) {
    int e = blockIdx.x * blockDim.x + threadIdx.x;
    if (e >= NEDGES) return;
    int s = src[e];
    int d = dst[e];
    float nm = g_dinv[s] * w[e] * g_dinv[d];
    int pos = atomicAdd(&g_cur[d], 1);
    g_csr_src[pos] = s;
    g_csr_nrm[pos] = nm;
}

// ---------------- GEMM: H = X[N,128] @ W[128,OUT] ----------------------------
template <int OUT>
__global__ void gemm_kernel(const float* __restrict__ X, const float* __restrict__ W,
                            float* __restrict__ H) {
    constexpr int IN = 128;
    constexpr int NCOL = OUT / 32;
    __shared__ __align__(16) float xs[IN][66];

    const int t = threadIdx.x;
    const int row0 = blockIdx.x * 64;

    for (int i = t; i < 64 * IN; i += 128) {
        int r = i >> 7, k = i & 127;
        int gr = row0 + r;
        xs[k][r] = (gr < NNODES) ? X[(size_t)gr * IN + k] : 0.0f;
    }
    __syncthreads();

    const int tx = t & 31;
    const int ty = t >> 5;

    unsigned long long acc[8][NCOL];
#pragma unroll
    for (int rp = 0; rp < 8; rp++)
#pragma unroll
        for (int j = 0; j < NCOL; j++) acc[rp][j] = 0ull;

#pragma unroll 2
    for (int k = 0; k < IN; k++) {
        unsigned long long w2[NCOL];
#pragma unroll
        for (int j = 0; j < NCOL; j++)
            w2[j] = pack_dup(W[(size_t)k * OUT + tx + 32 * j]);
#pragma unroll
        for (int rp = 0; rp < 8; rp++) {
            unsigned long long xv =
                *(const unsigned long long*)&xs[k][ty * 16 + 2 * rp];
#pragma unroll
            for (int j = 0; j < NCOL; j++) acc[rp][j] = fma2(xv, w2[j], acc[rp][j]);
        }
    }

#pragma unroll
    for (int rp = 0; rp < 8; rp++) {
        int r0 = row0 + ty * 16 + 2 * rp;
#pragma unroll
        for (int j = 0; j < NCOL; j++) {
            float lo, hi;
            unpack2(acc[rp][j], lo, hi);
            int c = tx + 32 * j;
            if (r0 < NNODES) H[(size_t)r0 * OUT + c] = lo;
            if (r0 + 1 < NNODES) H[(size_t)(r0 + 1) * OUT + c] = hi;
        }
    }
}

// ------- fused: gather-aggregate (CSR) + self-loop + bias + LN (+ReLU) -------
// Warp per destination node; gather loop unrolled x2 for MLP.
template <int DIM, bool RELU>
__global__ void agg_ln_kernel(const float* __restrict__ H, const float* __restrict__ b,
                              const float* __restrict__ gm, const float* __restrict__ bt,
                              float* __restrict__ O) {
    int gt = blockIdx.x * blockDim.x + threadIdx.x;
    int node = gt >> 5;
    if (node >= NNODES) return;
    int lane = gt & 31;

    float di = g_dinv[node];
    float d2 = di * di;
    int beg = g_off[node];
    int end = g_off[node + 1];

    if (DIM == 128) {
        int c = lane * 4;
        float4 hv = *(const float4*)(H + (size_t)node * 128 + c);
        float4 bv = *(const float4*)(b + c);
        float4 acc;
        acc.x = d2 * hv.x + bv.x;
        acc.y = d2 * hv.y + bv.y;
        acc.z = d2 * hv.z + bv.z;
        acc.w = d2 * hv.w + bv.w;

        int j = beg;
        // 2 edges per iteration for MLP
        for (; j + 1 < end; j += 2) {
            int sa = __ldg(&g_csr_src[j]);
            int sb = __ldg(&g_csr_src[j + 1]);
            float na = __ldg(&g_csr_nrm[j]);
            float nb = __ldg(&g_csr_nrm[j + 1]);
            float4 va = *(const float4*)(H + (size_t)sa * 128 + c);
            float4 vb = *(const float4*)(H + (size_t)sb * 128 + c);
            acc.x += na * va.x + nb * vb.x;
            acc.y += na * va.y + nb * vb.y;
            acc.z += na * va.z + nb * vb.z;
            acc.w += na * va.w + nb * vb.w;
        }
        if (j < end) {
            int s = __ldg(&g_csr_src[j]);
            float nm = __ldg(&g_csr_nrm[j]);
            float4 v = *(const float4*)(H + (size_t)s * 128 + c);
            acc.x += nm * v.x;
            acc.y += nm * v.y;
            acc.z += nm * v.z;
            acc.w += nm * v.w;
        }

        float s1 = acc.x + acc.y + acc.z + acc.w;
        float s2 = acc.x * acc.x + acc.y * acc.y + acc.z * acc.z + acc.w * acc.w;
#pragma unroll
        for (int o = 16; o > 0; o >>= 1) {
            s1 += __shfl_xor_sync(0xffffffffu, s1, o);
            s2 += __shfl_xor_sync(0xffffffffu, s2, o);
        }
        float mean = s1 * (1.0f / 128.0f);
        float var = s2 * (1.0f / 128.0f) - mean * mean;
        float inv = rsqrtf(var + LN_EPS);
        float4 gv = *(const float4*)(gm + c);
        float4 tv = *(const float4*)(bt + c);
        float4 o4;
        o4.x = (acc.x - mean) * inv * gv.x + tv.x;
        o4.y = (acc.y - mean) * inv * gv.y + tv.y;
        o4.z = (acc.z - mean) * inv * gv.z + tv.z;
        o4.w = (acc.w - mean) * inv * gv.w + tv.w;
        if (RELU) {
            o4.x = fmaxf(o4.x, 0.0f);
            o4.y = fmaxf(o4.y, 0.0f);
            o4.z = fmaxf(o4.z, 0.0f);
            o4.w = fmaxf(o4.w, 0.0f);
        }
        *(float4*)(O + (size_t)node * 128 + c) = o4;
    } else {   // DIM == 64
        int c = lane * 2;
        float2 hv = *(const float2*)(H + (size_t)node * 64 + c);
        float2 bv = *(const float2*)(b + c);
        float2 acc;
        acc.x = d2 * hv.x + bv.x;
        acc.y = d2 * hv.y + bv.y;

        int j = beg;
        for (; j + 1 < end; j += 2) {
            int sa = __ldg(&g_csr_src[j]);
            int sb = __ldg(&g_csr_src[j + 1]);
            float na = __ldg(&g_csr_nrm[j]);
            float nb = __ldg(&g_csr_nrm[j + 1]);
            float2 va = *(const float2*)(H + (size_t)sa * 64 + c);
            float2 vb = *(const float2*)(H + (size_t)sb * 64 + c);
            acc.x += na * va.x + nb * vb.x;
            acc.y += na * va.y + nb * vb.y;
        }
        if (j < end) {
            int s = __ldg(&g_csr_src[j]);
            float nm = __ldg(&g_csr_nrm[j]);
            float2 v = *(const float2*)(H + (size_t)s * 64 + c);
            acc.x += nm * v.x;
            acc.y += nm * v.y;
        }

        float s1 = acc.x + acc.y;
        float s2 = acc.x * acc.x + acc.y * acc.y;
#pragma unroll
        for (int o = 16; o > 0; o >>= 1) {
            s1 += __shfl_xor_sync(0xffffffffu, s1, o);
            s2 += __shfl_xor_sync(0xffffffffu, s2, o);
        }
        float mean = s1 * (1.0f / 64.0f);
        float var = s2 * (1.0f / 64.0f) - mean * mean;
        float inv = rsqrtf(var + LN_EPS);
        float2 gv = *(const float2*)(gm + c);
        float2 tv = *(const float2*)(bt + c);
        float2 o2;
        o2.x = (acc.x - mean) * inv * gv.x + tv.x;
        o2.y = (acc.y - mean) * inv * gv.y + tv.y;
        if (RELU) {
            o2.x = fmaxf(o2.x, 0.0f);
            o2.y = fmaxf(o2.y, 0.0f);
        }
        *(float2*)(O + (size_t)node * 64 + c) = o2;
    }
}

// ---------------- host launch -------------------------------------------------
extern "C" void kernel_launch(void* const* d_in, const int* in_sizes, int n_in,
                              void* d_out, int out_size) {
    const float* x  = (const float*)d_in[0];
    const int*   ei = (const int*)d_in[1];
    const float* ew = (const float*)d_in[2];
    const float* W1 = (const float*)d_in[3];
    const float* b1 = (const float*)d_in[4];
    const float* g1 = (const float*)d_in[5];
    const float* t1 = (const float*)d_in[6];
    const float* W2 = (const float*)d_in[7];
    const float* b2 = (const float*)d_in[8];
    const float* g2 = (const float*)d_in[9];
    const float* t2 = (const float*)d_in[10];
    const float* W3 = (const float*)d_in[11];
    const float* b3 = (const float*)d_in[12];
    const float* g3 = (const float*)d_in[13];
    const float* t3 = (const float*)d_in[14];
    const int* src = ei;
    const int* dst = ei + NEDGES;
    float* out = (float*)d_out;

    float *h, *feat;
    cudaGetSymbolAddress((void**)&h, g_h);
    cudaGetSymbolAddress((void**)&feat, g_feat);

    const int TB = 256;
    const int nblk_N = (NNODES + TB - 1) / TB;
    const int nblk_E = (NEDGES + TB - 1) / TB;
    const int nblk_row = (NNODES * 32 + TB - 1) / TB;    // warp per node
    const int nblk_gemm = (NNODES + 63) / 64;

    // precompute: weighted degree + counts, hierarchical scan (+dinv), CSR fill
    init_counts_kernel<<<nblk_N, TB>>>();
    count_kernel<<<nblk_E, TB>>>(dst, ew);
    scan_block_kernel<<<SCAN_NB, SCAN_BS>>>();
    scan_tops_kernel<<<1, 128>>>();
    scan_add_kernel<<<SCAN_NB, SCAN_BS>>>();
    fill_kernel<<<nblk_E, TB>>>(src, dst, ew);

    // layer 1
    gemm_kernel<128><<<nblk_gemm, 128>>>(x, W1, h);
    agg_ln_kernel<128, true><<<nblk_row, TB>>>(h, b1, g1, t1, feat);

    // layer 2
    gemm_kernel<128><<<nblk_gemm, 128>>>(feat, W2, h);
    agg_ln_kernel<128, true><<<nblk_row, TB>>>(h, b2, g2, t2, feat);

    // layer 3 (dout = 64, no relu), output straight to d_out
    gemm_kernel<64><<<nblk_gemm, 128>>>(feat, W3, h);
    agg_ln_kernel<64, false><<<nblk_row, TB>>>(h, b3, g3, t3, out);
}

// round 4
// speedup vs baseline: 1.9252x; 1.1887x over previous
#include <cuda_runtime.h>
#include <cuda_fp16.h>
#include <cstdint>

#define NNODES 50000
#define NEDGES 800000
#define LN_EPS 1e-5f

#define SCAN_BS 512
#define SCAN_NB ((NNODES + SCAN_BS - 1) / SCAN_BS)   // 98

// ---------------- scratch (static device globals; no runtime alloc) ----------
__device__ __half g_h16[NNODES * 128];   // GEMM output (fp16 messages)
__device__ float  g_feat[NNODES * 128];  // LN output (next layer input, fp32)
__device__ float  g_deg[NNODES];
__device__ float  g_dinv[NNODES];
__device__ int    g_cnt[NNODES];
__device__ int    g_off[NNODES + 1];
__device__ int    g_cur[NNODES];
__device__ int    g_bsum[SCAN_NB];
__device__ int    g_bpre[SCAN_NB];
__device__ int    g_csr_src[NEDGES];
__device__ float  g_csr_nrm[NEDGES];

// ---------------- f32x2 packed helpers --------------------------------------
__device__ __forceinline__ unsigned long long fma2(unsigned long long a,
                                                   unsigned long long b,
                                                   unsigned long long c) {
    unsigned long long d;
    asm("fma.rn.f32x2 %0, %1, %2, %3;" : "=l"(d) : "l"(a), "l"(b), "l"(c));
    return d;
}
__device__ __forceinline__ unsigned long long pack_dup(float v) {
    unsigned long long r;
    asm("mov.b64 %0, {%1, %1};" : "=l"(r) : "f"(v));
    return r;
}
__device__ __forceinline__ void unpack2(unsigned long long p, float& lo, float& hi) {
    asm("mov.b64 {%0, %1}, %2;" : "=f"(lo), "=f"(hi) : "l"(p));
}

// ---------------- precompute ------------------------------------------------
__global__ void init_counts_kernel() {
    int i = blockIdx.x * blockDim.x + threadIdx.x;
    if (i < NNODES) {
        g_deg[i] = 1.0f;   // self-loop weight
        g_cnt[i] = 0;
    }
}

__global__ void count_kernel(const int* __restrict__ dst, const float* __restrict__ w) {
    int e = blockIdx.x * blockDim.x + threadIdx.x;
    if (e < NEDGES) {
        int d = dst[e];
        atomicAdd(&g_deg[d], w[e]);
        atomicAdd(&g_cnt[d], 1);
    }
}

// phase 1: per-block exclusive scan of g_cnt -> g_off (local), total -> g_bsum
__global__ void scan_block_kernel() {
    __shared__ int wsum[SCAN_BS / 32];
    int t = threadIdx.x;
    int lane = t & 31;
    int wid = t >> 5;
    int i = blockIdx.x * SCAN_BS + t;
    int v = (i < NNODES) ? g_cnt[i] : 0;

    int x = v;
#pragma unroll
    for (int o = 1; o < 32; o <<= 1) {
        int y = __shfl_up_sync(0xffffffffu, x, o);
        if (lane >= o) x += y;
    }
    if (lane == 31) wsum[wid] = x;
    __syncthreads();
    if (wid == 0) {
        int s = (lane < SCAN_BS / 32) ? wsum[lane] : 0;
#pragma unroll
        for (int o = 1; o < SCAN_BS / 32; o <<= 1) {
            int y = __shfl_up_sync(0xffffffffu, s, o);
            if (lane >= o) s += y;
        }
        if (lane < SCAN_BS / 32) wsum[lane] = s;
    }
    __syncthreads();
    int wpre = (wid == 0) ? 0 : wsum[wid - 1];
    int excl = wpre + x - v;
    if (i < NNODES) g_off[i] = excl;
    if (t == SCAN_BS - 1) g_bsum[blockIdx.x] = wpre + x;
}

// phase 2: single block scans block totals
__global__ void scan_tops_kernel() {
    __shared__ int s[128];
    int t = threadIdx.x;
    s[t] = (t < SCAN_NB) ? g_bsum[t] : 0;
    __syncthreads();
#pragma unroll
    for (int o = 1; o < 128; o <<= 1) {
        int v = s[t];
        int u = (t >= o) ? s[t - o] : 0;
        __syncthreads();
        s[t] = v + u;
        __syncthreads();
    }
    if (t < SCAN_NB) g_bpre[t] = (t == 0) ? 0 : s[t - 1];
}

// phase 3: add block prefix, init cursors; fused dinv
__global__ void scan_add_kernel() {
    int i = blockIdx.x * SCAN_BS + threadIdx.x;
    if (i < NNODES) {
        int off = g_off[i] + g_bpre[blockIdx.x];
        g_off[i] = off;
        g_cur[i] = off;
        g_dinv[i] = rsqrtf(g_deg[i]);
    }
    if (i == 0) g_off[NNODES] = NEDGES;
}

__global__ void fill_kernel(const int* __restrict__ src, const int* __restrict__ dst,
                            const float* __restrict__ w) {
    int e = blockIdx.x * blockDim.x + threadIdx.x;
    if (e >= NEDGES) return;
    int s = src[e];
    int d = dst[e];
    float nm = g_dinv[s] * w[e] * g_dinv[d];
    int pos = atomicAdd(&g_cur[d], 1);
    g_csr_src[pos] = s;
    g_csr_nrm[pos] = nm;
}

// ---------------- GEMM: H16 = fp16(X[N,128] @ W[128,OUT]) --------------------
// 256 threads = 32 tx (column pairs) x 8 ty (row groups of 8).
// f32x2 accumulators pack ADJACENT COLUMNS -> coalesced half2 stores.
template <int OUT>
__global__ void gemm_kernel(const float* __restrict__ X, const float* __restrict__ W,
                            __half* __restrict__ H) {
    constexpr int IN = 128;
    constexpr int NCOL = OUT / 64;            // col-pairs per thread (2 or 1)
    __shared__ __align__(16) float xs[64][IN];

    const int t = threadIdx.x;
    const int row0 = blockIdx.x * 64;

    for (int i = t; i < 64 * IN; i += 256) {
        int r = i >> 7, k = i & 127;
        int gr = row0 + r;
        xs[r][k] = (gr < NNODES) ? X[(size_t)gr * IN + k] : 0.0f;
    }
    __syncthreads();

    const int tx = t & 31;
    const int ty = t >> 5;

    unsigned long long acc[8][NCOL];
#pragma unroll
    for (int i = 0; i < 8; i++)
#pragma unroll
        for (int j = 0; j < NCOL; j++) acc[i][j] = 0ull;

#pragma unroll 2
    for (int k = 0; k < IN; k++) {
        unsigned long long w2[NCOL];
#pragma unroll
        for (int j = 0; j < NCOL; j++)
            w2[j] = *(const unsigned long long*)&W[(size_t)k * OUT + 2 * tx + 64 * j];
#pragma unroll
        for (int i = 0; i < 8; i++) {
            unsigned long long xv = pack_dup(xs[ty * 8 + i][k]);
#pragma unroll
            for (int j = 0; j < NCOL; j++) acc[i][j] = fma2(xv, w2[j], acc[i][j]);
        }
    }

#pragma unroll
    for (int i = 0; i < 8; i++) {
        int r = row0 + ty * 8 + i;
        if (r < NNODES) {
#pragma unroll
            for (int j = 0; j < NCOL; j++) {
                float lo, hi;
                unpack2(acc[i][j], lo, hi);
                __half2 hv = __floats2half2_rn(lo, hi);
                *(__half2*)(H + (size_t)r * OUT + 2 * tx + 64 * j) = hv;
            }
        }
    }
}

// ------- fused: gather-aggregate (CSR, fp16 msgs) + self + bias + LN ---------
// Warp per destination node; gather loop unrolled x4 for MLP.
__device__ __forceinline__ float4 ld_h16_row(const __half* H, int row, int lane) {
    uint2 u = *(const uint2*)(H + (size_t)row * 128 + lane * 4);
    __half2 h0 = *(__half2*)&u.x;
    __half2 h1 = *(__half2*)&u.y;
    float2 a = __half22float2(h0);
    float2 b = __half22float2(h1);
    return make_float4(a.x, a.y, b.x, b.y);
}
__device__ __forceinline__ float2 ld_h16_row64(const __half* H, int row, int lane) {
    uint32_t u = *(const uint32_t*)(H + (size_t)row * 64 + lane * 2);
    return __half22float2(*(__half2*)&u);
}

template <int DIM, bool RELU>
__global__ void agg_ln_kernel(const __half* __restrict__ H, const float* __restrict__ b,
                              const float* __restrict__ gm, const float* __restrict__ bt,
                              float* __restrict__ O) {
    int gt = blockIdx.x * blockDim.x + threadIdx.x;
    int node = gt >> 5;
    if (node >= NNODES) return;
    int lane = gt & 31;

    float di = g_dinv[node];
    float d2 = di * di;
    int beg = g_off[node];
    int end = g_off[node + 1];

    if (DIM == 128) {
        int c = lane * 4;
        float4 hv = ld_h16_row(H, node, lane);
        float4 bv = *(const float4*)(b + c);
        float4 acc;
        acc.x = d2 * hv.x + bv.x;
        acc.y = d2 * hv.y + bv.y;
        acc.z = d2 * hv.z + bv.z;
        acc.w = d2 * hv.w + bv.w;

        int j = beg;
        for (; j + 3 < end; j += 4) {
            int s0 = __ldg(&g_csr_src[j]);
            int s1 = __ldg(&g_csr_src[j + 1]);
            int s2 = __ldg(&g_csr_src[j + 2]);
            int s3 = __ldg(&g_csr_src[j + 3]);
            float n0 = __ldg(&g_csr_nrm[j]);
            float n1 = __ldg(&g_csr_nrm[j + 1]);
            float n2 = __ldg(&g_csr_nrm[j + 2]);
            float n3 = __ldg(&g_csr_nrm[j + 3]);
            float4 v0 = ld_h16_row(H, s0, lane);
            float4 v1 = ld_h16_row(H, s1, lane);
            float4 v2 = ld_h16_row(H, s2, lane);
            float4 v3 = ld_h16_row(H, s3, lane);
            acc.x += n0 * v0.x + n1 * v1.x + n2 * v2.x + n3 * v3.x;
            acc.y += n0 * v0.y + n1 * v1.y + n2 * v2.y + n3 * v3.y;
            acc.z += n0 * v0.z + n1 * v1.z + n2 * v2.z + n3 * v3.z;
            acc.w += n0 * v0.w + n1 * v1.w + n2 * v2.w + n3 * v3.w;
        }
        for (; j < end; j++) {
            int s = __ldg(&g_csr_src[j]);
            float nm = __ldg(&g_csr_nrm[j]);
            float4 v = ld_h16_row(H, s, lane);
            acc.x += nm * v.x;
            acc.y += nm * v.y;
            acc.z += nm * v.z;
            acc.w += nm * v.w;
        }

        float s1 = acc.x + acc.y + acc.z + acc.w;
        float s2 = acc.x * acc.x + acc.y * acc.y + acc.z * acc.z + acc.w * acc.w;
#pragma unroll
        for (int o = 16; o > 0; o >>= 1) {
            s1 += __shfl_xor_sync(0xffffffffu, s1, o);
            s2 += __shfl_xor_sync(0xffffffffu, s2, o);
        }
        float mean = s1 * (1.0f / 128.0f);
        float var = s2 * (1.0f / 128.0f) - mean * mean;
        float inv = rsqrtf(var + LN_EPS);
        float4 gv = *(const float4*)(gm + c);
        float4 tv = *(const float4*)(bt + c);
        float4 o4;
        o4.x = (acc.x - mean) * inv * gv.x + tv.x;
        o4.y = (acc.y - mean) * inv * gv.y + tv.y;
        o4.z = (acc.z - mean) * inv * gv.z + tv.z;
        o4.w = (acc.w - mean) * inv * gv.w + tv.w;
        if (RELU) {
            o4.x = fmaxf(o4.x, 0.0f);
            o4.y = fmaxf(o4.y, 0.0f);
            o4.z = fmaxf(o4.z, 0.0f);
            o4.w = fmaxf(o4.w, 0.0f);
        }
        *(float4*)(O + (size_t)node * 128 + c) = o4;
    } else {   // DIM == 64
        int c = lane * 2;
        float2 hv = ld_h16_row64(H, node, lane);
        float2 bv = *(const float2*)(b + c);
        float2 acc;
        acc.x = d2 * hv.x + bv.x;
        acc.y = d2 * hv.y + bv.y;

        int j = beg;
        for (; j + 3 < end; j += 4) {
            int s0 = __ldg(&g_csr_src[j]);
            int s1 = __ldg(&g_csr_src[j + 1]);
            int s2 = __ldg(&g_csr_src[j + 2]);
            int s3 = __ldg(&g_csr_src[j + 3]);
            float n0 = __ldg(&g_csr_nrm[j]);
            float n1 = __ldg(&g_csr_nrm[j + 1]);
            float n2 = __ldg(&g_csr_nrm[j + 2]);
            float n3 = __ldg(&g_csr_nrm[j + 3]);
            float2 v0 = ld_h16_row64(H, s0, lane);
            float2 v1 = ld_h16_row64(H, s1, lane);
            float2 v2 = ld_h16_row64(H, s2, lane);
            float2 v3 = ld_h16_row64(H, s3, lane);
            acc.x += n0 * v0.x + n1 * v1.x + n2 * v2.x + n3 * v3.x;
            acc.y += n0 * v0.y + n1 * v1.y + n2 * v2.y + n3 * v3.y;
        }
        for (; j < end; j++) {
            int s = __ldg(&g_csr_src[j]);
            float nm = __ldg(&g_csr_nrm[j]);
            float2 v = ld_h16_row64(H, s, lane);
            acc.x += nm * v.x;
            acc.y += nm * v.y;
        }

        float s1 = acc.x + acc.y;
        float s2 = acc.x * acc.x + acc.y * acc.y;
#pragma unroll
        for (int o = 16; o > 0; o >>= 1) {
            s1 += __shfl_xor_sync(0xffffffffu, s1, o);
            s2 += __shfl_xor_sync(0xffffffffu, s2, o);
        }
        float mean = s1 * (1.0f / 64.0f);
        float var = s2 * (1.0f / 64.0f) - mean * mean;
        float inv = rsqrtf(var + LN_EPS);
        float2 gv = *(const float2*)(gm + c);
        float2 tv = *(const float2*)(bt + c);
        float2 o2;
        o2.x = (acc.x - mean) * inv * gv.x + tv.x;
        o2.y = (acc.y - mean) * inv * gv.y + tv.y;
        if (RELU) {
            o2.x = fmaxf(o2.x, 0.0f);
            o2.y = fmaxf(o2.y, 0.0f);
        }
        *(float2*)(O + (size_t)node * 64 + c) = o2;
    }
}

// ---------------- host launch -------------------------------------------------
extern "C" void kernel_launch(void* const* d_in, const int* in_sizes, int n_in,
                              void* d_out, int out_size) {
    const float* x  = (const float*)d_in[0];
    const int*   ei = (const int*)d_in[1];
    const float* ew = (const float*)d_in[2];
    const float* W1 = (const float*)d_in[3];
    const float* b1 = (const float*)d_in[4];
    const float* g1 = (const float*)d_in[5];
    const float* t1 = (const float*)d_in[6];
    const float* W2 = (const float*)d_in[7];
    const float* b2 = (const float*)d_in[8];
    const float* g2 = (const float*)d_in[9];
    const float* t2 = (const float*)d_in[10];
    const float* W3 = (const float*)d_in[11];
    const float* b3 = (const float*)d_in[12];
    const float* g3 = (const float*)d_in[13];
    const float* t3 = (const float*)d_in[14];
    const int* src = ei;
    const int* dst = ei + NEDGES;
    float* out = (float*)d_out;

    __half* h16;
    float* feat;
    cudaGetSymbolAddress((void**)&h16, g_h16);
    cudaGetSymbolAddress((void**)&feat, g_feat);

    const int TB = 256;
    const int nblk_N = (NNODES + TB - 1) / TB;
    const int nblk_E = (NEDGES + TB - 1) / TB;
    const int nblk_row = (NNODES * 32 + TB - 1) / TB;    // warp per node
    const int nblk_gemm = (NNODES + 63) / 64;

    // precompute
    init_counts_kernel<<<nblk_N, TB>>>();
    count_kernel<<<nblk_E, TB>>>(dst, ew);
    scan_block_kernel<<<SCAN_NB, SCAN_BS>>>();
    scan_tops_kernel<<<1, 128>>>();
    scan_add_kernel<<<SCAN_NB, SCAN_BS>>>();
    fill_kernel<<<nblk_E, TB>>>(src, dst, ew);

    // layer 1
    gemm_kernel<128><<<nblk_gemm, 256>>>(x, W1, h16);
    agg_ln_kernel<128, true><<<nblk_row, TB>>>(h16, b1, g1, t1, feat);

    // layer 2
    gemm_kernel<128><<<nblk_gemm, 256>>>(feat, W2, h16);
    agg_ln_kernel<128, true><<<nblk_row, TB>>>(h16, b2, g2, t2, feat);

    // layer 3 (dout = 64, no relu), output straight to d_out
    gemm_kernel<64><<<nblk_gemm, 256>>>(feat, W3, h16);
    agg_ln_kernel<64, false><<<nblk_row, TB>>>(h16, b3, g3, t3, out);
}

// round 5
// speedup vs baseline: 2.2179x; 1.1520x over previous
#include <cuda_runtime.h>
#include <cuda_fp16.h>
#include <mma.h>
#include <cstdint>

using namespace nvcuda;

#define NNODES 50000
#define NEDGES 800000
#define LN_EPS 1e-5f

#define SCAN_BS 512
#define SCAN_NB ((NNODES + SCAN_BS - 1) / SCAN_BS)   // 98

// ---------------- scratch (static device globals; no runtime alloc) ----------
__device__ __align__(32) __half g_x16[NNODES * 128];   // fp16 copy of input x
__device__ __align__(32) __half g_h16[NNODES * 128];   // GEMM output (fp16 messages)
__device__ __align__(32) __half g_feat16[NNODES * 128];// LN output (fp16, next layer A)
__device__ __align__(32) __half g_w16_1[128 * 128];
__device__ __align__(32) __half g_w16_2[128 * 128];
__device__ __align__(32) __half g_w16_3[128 * 64];
__device__ float  g_deg[NNODES];
__device__ float  g_dinv[NNODES];
__device__ int    g_cnt[NNODES];
__device__ int    g_off[NNODES + 1];
__device__ int    g_cur[NNODES];
__device__ int    g_bsum[SCAN_NB];
__device__ int    g_bpre[SCAN_NB];
__device__ int    g_csr_src[NEDGES];
__device__ float  g_csr_nrm[NEDGES];

// ---------------- conversions -------------------------------------------------
__global__ void cvt_x_kernel(const float* __restrict__ x) {
    int i = blockIdx.x * blockDim.x + threadIdx.x;   // over NNODES*32 float4s
    if (i < NNODES * 32) {
        float4 v = ((const float4*)x)[i];
        __half2 a = __floats2half2_rn(v.x, v.y);
        __half2 b = __floats2half2_rn(v.z, v.w);
        uint2 u;
        u.x = *(uint32_t*)&a;
        u.y = *(uint32_t*)&b;
        ((uint2*)g_x16)[i] = u;
    }
}

__global__ void cvt_w_kernel(const float* __restrict__ W1, const float* __restrict__ W2,
                             const float* __restrict__ W3) {
    int i = blockIdx.x * blockDim.x + threadIdx.x;
    if (i < 16384) g_w16_1[i] = __float2half(W1[i]);
    else if (i < 32768) g_w16_2[i - 16384] = __float2half(W2[i - 16384]);
    else if (i < 40960) g_w16_3[i - 32768] = __float2half(W3[i - 32768]);
}

// ---------------- precompute ------------------------------------------------
__global__ void init_counts_kernel() {
    int i = blockIdx.x * blockDim.x + threadIdx.x;
    if (i < NNODES) {
        g_deg[i] = 1.0f;   // self-loop weight
        g_cnt[i] = 0;
    }
}

__global__ void count_kernel(const int* __restrict__ dst, const float* __restrict__ w) {
    int e = blockIdx.x * blockDim.x + threadIdx.x;
    if (e < NEDGES) {
        int d = dst[e];
        atomicAdd(&g_deg[d], w[e]);
        atomicAdd(&g_cnt[d], 1);
    }
}

__global__ void scan_block_kernel() {
    __shared__ int wsum[SCAN_BS / 32];
    int t = threadIdx.x;
    int lane = t & 31;
    int wid = t >> 5;
    int i = blockIdx.x * SCAN_BS + t;
    int v = (i < NNODES) ? g_cnt[i] : 0;

    int x = v;
#pragma unroll
    for (int o = 1; o < 32; o <<= 1) {
        int y = __shfl_up_sync(0xffffffffu, x, o);
        if (lane >= o) x += y;
    }
    if (lane == 31) wsum[wid] = x;
    __syncthreads();
    if (wid == 0) {
        int s = (lane < SCAN_BS / 32) ? wsum[lane] : 0;
#pragma unroll
        for (int o = 1; o < SCAN_BS / 32; o <<= 1) {
            int y = __shfl_up_sync(0xffffffffu, s, o);
            if (lane >= o) s += y;
        }
        if (lane < SCAN_BS / 32) wsum[lane] = s;
    }
    __syncthreads();
    int wpre = (wid == 0) ? 0 : wsum[wid - 1];
    int excl = wpre + x - v;
    if (i < NNODES) g_off[i] = excl;
    if (t == SCAN_BS - 1) g_bsum[blockIdx.x] = wpre + x;
}

__global__ void scan_tops_kernel() {
    __shared__ int s[128];
    int t = threadIdx.x;
    s[t] = (t < SCAN_NB) ? g_bsum[t] : 0;
    __syncthreads();
#pragma unroll
    for (int o = 1; o < 128; o <<= 1) {
        int v = s[t];
        int u = (t >= o) ? s[t - o] : 0;
        __syncthreads();
        s[t] = v + u;
        __syncthreads();
    }
    if (t < SCAN_NB) g_bpre[t] = (t == 0) ? 0 : s[t - 1];
}

__global__ void scan_add_kernel() {
    int i = blockIdx.x * SCAN_BS + threadIdx.x;
    if (i < NNODES) {
        int off = g_off[i] + g_bpre[blockIdx.x];
        g_off[i] = off;
        g_cur[i] = off;
        g_dinv[i] = rsqrtf(g_deg[i]);
    }
    if (i == 0) g_off[NNODES] = NEDGES;
}

__global__ void fill_kernel(const int* __restrict__ src, const int* __restrict__ dst,
                            const float* __restrict__ w) {
    int e = blockIdx.x * blockDim.x + threadIdx.x;
    if (e >= NEDGES) return;
    int s = src[e];
    int d = dst[e];
    float nm = g_dinv[s] * w[e] * g_dinv[d];
    int pos = atomicAdd(&g_cur[d], 1);
    g_csr_src[pos] = s;
    g_csr_nrm[pos] = nm;
}

// ---------------- tensor-core GEMM: H16 = fp16(A16[N,128] @ W16[128,OUT]) ----
// Block = 64 rows; 8 warps = 4 row-groups x 2 col-groups.
template <int OUT>
__global__ void gemm_wmma_kernel(const __half* __restrict__ A,
                                 const __half* __restrict__ W,
                                 __half* __restrict__ H) {
    constexpr int IN = 128;
    constexpr int ALD = IN + 16;     // 144 halves = 288B, 32B-multiple
    constexpr int CLD = OUT + 8;     // floats; 136*4=544B / 72*4=288B, 32B-multiples
    constexpr int COLW = OUT / 2;    // cols per warp col-group (64 or 32)
    constexpr int NF = COLW / 16;    // accum frags per warp (4 or 2)
    constexpr int ABYTES = 64 * ALD * 2;
    constexpr int CBYTES = 64 * CLD * 4;
    constexpr int BUFB = (ABYTES > CBYTES) ? ABYTES : CBYTES;

    __shared__ __align__(32) char buf[BUFB];
    __half (*As)[ALD] = (__half(*)[ALD])buf;
    float (*Cs)[CLD] = (float(*)[CLD])buf;

    const int t = threadIdx.x;
    const int row0 = blockIdx.x * 64;

    // load A tile (8 halves per thread-iter, coalesced)
    for (int i = t; i < 64 * (IN / 8); i += 256) {
        int r = i >> 4;               // IN/8 = 16
        int kc = (i & 15) * 8;
        int gr = row0 + r;
        uint4 v = make_uint4(0u, 0u, 0u, 0u);
        if (gr < NNODES) v = *(const uint4*)(A + (size_t)gr * IN + kc);
        *(uint4*)&As[r][kc] = v;
    }
    __syncthreads();

    const int w = t >> 5;
    const int wr = w >> 1;
    const int wc = w & 1;

    wmma::fragment<wmma::accumulator, 16, 16, 16, float> cf[NF];
#pragma unroll
    for (int j = 0; j < NF; j++) wmma::fill_fragment(cf[j], 0.0f);

    wmma::fragment<wmma::matrix_a, 16, 16, 16, __half, wmma::row_major> af;
    wmma::fragment<wmma::matrix_b, 16, 16, 16, __half, wmma::row_major> bf;

#pragma unroll
    for (int k = 0; k < IN; k += 16) {
        wmma::load_matrix_sync(af, &As[wr * 16][k], ALD);
#pragma unroll
        for (int j = 0; j < NF; j++) {
            wmma::load_matrix_sync(bf, W + (size_t)k * OUT + wc * COLW + j * 16, OUT);
            wmma::mma_sync(cf[j], af, bf, cf[j]);
        }
    }

    __syncthreads();   // all warps done reading As before aliasing as Cs
#pragma unroll
    for (int j = 0; j < NF; j++)
        wmma::store_matrix_sync(&Cs[wr * 16][wc * COLW + j * 16], cf[j], CLD,
                                wmma::mem_row_major);
    __syncthreads();

    // convert + coalesced half2 store
    for (int i = t; i < 64 * (OUT / 2); i += 256) {
        int r = i / (OUT / 2);
        int c = (i % (OUT / 2)) * 2;
        int gr = row0 + r;
        if (gr < NNODES) {
            __half2 hv = __floats2half2_rn(Cs[r][c], Cs[r][c + 1]);
            *(__half2*)(H + (size_t)gr * OUT + c) = hv;
        }
    }
}

// ------- fused: gather-aggregate (CSR, fp16 msgs) + self + bias + LN ---------
__device__ __forceinline__ float4 ld_h16_row(const __half* H, int row, int lane) {
    uint2 u = *(const uint2*)(H + (size_t)row * 128 + lane * 4);
    float2 a = __half22float2(*(__half2*)&u.x);
    float2 b = __half22float2(*(__half2*)&u.y);
    return make_float4(a.x, a.y, b.x, b.y);
}
__device__ __forceinline__ float2 ld_h16_row64(const __half* H, int row, int lane) {
    uint32_t u = *(const uint32_t*)(H + (size_t)row * 64 + lane * 2);
    return __half22float2(*(__half2*)&u);
}

// HALF_OUT: write O as fp16 (feat) else fp32 (final output)
template <int DIM, bool RELU, bool HALF_OUT>
__global__ void agg_ln_kernel(const __half* __restrict__ H, const float* __restrict__ b,
                              const float* __restrict__ gm, const float* __restrict__ bt,
                              void* __restrict__ Ov) {
    int gt = blockIdx.x * blockDim.x + threadIdx.x;
    int node = gt >> 5;
    if (node >= NNODES) return;
    int lane = gt & 31;

    float di = g_dinv[node];
    float d2 = di * di;
    int beg = g_off[node];
    int end = g_off[node + 1];

    if (DIM == 128) {
        int c = lane * 4;
        float4 hv = ld_h16_row(H, node, lane);
        float4 bv = *(const float4*)(b + c);
        float4 acc;
        acc.x = d2 * hv.x + bv.x;
        acc.y = d2 * hv.y + bv.y;
        acc.z = d2 * hv.z + bv.z;
        acc.w = d2 * hv.w + bv.w;

        int j = beg;
        for (; j + 3 < end; j += 4) {
            int s0 = __ldg(&g_csr_src[j]);
            int s1 = __ldg(&g_csr_src[j + 1]);
            int s2 = __ldg(&g_csr_src[j + 2]);
            int s3 = __ldg(&g_csr_src[j + 3]);
            float n0 = __ldg(&g_csr_nrm[j]);
            float n1 = __ldg(&g_csr_nrm[j + 1]);
            float n2 = __ldg(&g_csr_nrm[j + 2]);
            float n3 = __ldg(&g_csr_nrm[j + 3]);
            float4 v0 = ld_h16_row(H, s0, lane);
            float4 v1 = ld_h16_row(H, s1, lane);
            float4 v2 = ld_h16_row(H, s2, lane);
            float4 v3 = ld_h16_row(H, s3, lane);
            acc.x += n0 * v0.x + n1 * v1.x + n2 * v2.x + n3 * v3.x;
            acc.y += n0 * v0.y + n1 * v1.y + n2 * v2.y + n3 * v3.y;
            acc.z += n0 * v0.z + n1 * v1.z + n2 * v2.z + n3 * v3.z;
            acc.w += n0 * v0.w + n1 * v1.w + n2 * v2.w + n3 * v3.w;
        }
        for (; j < end; j++) {
            int s = __ldg(&g_csr_src[j]);
            float nm = __ldg(&g_csr_nrm[j]);
            float4 v = ld_h16_row(H, s, lane);
            acc.x += nm * v.x;
            acc.y += nm * v.y;
            acc.z += nm * v.z;
            acc.w += nm * v.w;
        }

        float s1 = acc.x + acc.y + acc.z + acc.w;
        float s2 = acc.x * acc.x + acc.y * acc.y + acc.z * acc.z + acc.w * acc.w;
#pragma unroll
        for (int o = 16; o > 0; o >>= 1) {
            s1 += __shfl_xor_sync(0xffffffffu, s1, o);
            s2 += __shfl_xor_sync(0xffffffffu, s2, o);
        }
        float mean = s1 * (1.0f / 128.0f);
        float var = s2 * (1.0f / 128.0f) - mean * mean;
        float inv = rsqrtf(var + LN_EPS);
        float4 gv = *(const float4*)(gm + c);
        float4 tv = *(const float4*)(bt + c);
        float4 o4;
        o4.x = (acc.x - mean) * inv * gv.x + tv.x;
        o4.y = (acc.y - mean) * inv * gv.y + tv.y;
        o4.z = (acc.z - mean) * inv * gv.z + tv.z;
        o4.w = (acc.w - mean) * inv * gv.w + tv.w;
        if (RELU) {
            o4.x = fmaxf(o4.x, 0.0f);
            o4.y = fmaxf(o4.y, 0.0f);
            o4.z = fmaxf(o4.z, 0.0f);
            o4.w = fmaxf(o4.w, 0.0f);
        }
        if (HALF_OUT) {
            __half* O = (__half*)Ov;
            __half2 ha = __floats2half2_rn(o4.x, o4.y);
            __half2 hb = __floats2half2_rn(o4.z, o4.w);
            uint2 u;
            u.x = *(uint32_t*)&ha;
            u.y = *(uint32_t*)&hb;
            *(uint2*)(O + (size_t)node * 128 + c) = u;
        } else {
            float* O = (float*)Ov;
            *(float4*)(O + (size_t)node * 128 + c) = o4;
        }
    } else {   // DIM == 64
        int c = lane * 2;
        float2 hv = ld_h16_row64(H, node, lane);
        float2 bv = *(const float2*)(b + c);
        float2 acc;
        acc.x = d2 * hv.x + bv.x;
        acc.y = d2 * hv.y + bv.y;

        int j = beg;
        for (; j + 3 < end; j += 4) {
            int s0 = __ldg(&g_csr_src[j]);
            int s1 = __ldg(&g_csr_src[j + 1]);
            int s2 = __ldg(&g_csr_src[j + 2]);
            int s3 = __ldg(&g_csr_src[j + 3]);
            float n0 = __ldg(&g_csr_nrm[j]);
            float n1 = __ldg(&g_csr_nrm[j + 1]);
            float n2 = __ldg(&g_csr_nrm[j + 2]);
            float n3 = __ldg(&g_csr_nrm[j + 3]);
            float2 v0 = ld_h16_row64(H, s0, lane);
            float2 v1 = ld_h16_row64(H, s1, lane);
            float2 v2 = ld_h16_row64(H, s2, lane);
            float2 v3 = ld_h16_row64(H, s3, lane);
            acc.x += n0 * v0.x + n1 * v1.x + n2 * v2.x + n3 * v3.x;
            acc.y += n0 * v0.y + n1 * v1.y + n2 * v2.y + n3 * v3.y;
        }
        for (; j < end; j++) {
            int s = __ldg(&g_csr_src[j]);
            float nm = __ldg(&g_csr_nrm[j]);
            float2 v = ld_h16_row64(H, s, lane);
            acc.x += nm * v.x;
            acc.y += nm * v.y;
        }

        float s1 = acc.x + acc.y;
        float s2 = acc.x * acc.x + acc.y * acc.y;
#pragma unroll
        for (int o = 16; o > 0; o >>= 1) {
            s1 += __shfl_xor_sync(0xffffffffu, s1, o);
            s2 += __shfl_xor_sync(0xffffffffu, s2, o);
        }
        float mean = s1 * (1.0f / 64.0f);
        float var = s2 * (1.0f / 64.0f) - mean * mean;
        float inv = rsqrtf(var + LN_EPS);
        float2 gv = *(const float2*)(gm + c);
        float2 tv = *(const float2*)(bt + c);
        float2 o2;
        o2.x = (acc.x - mean) * inv * gv.x + tv.x;
        o2.y = (acc.y - mean) * inv * gv.y + tv.y;
        if (RELU) {
            o2.x = fmaxf(o2.x, 0.0f);
            o2.y = fmaxf(o2.y, 0.0f);
        }
        float* O = (float*)Ov;
        *(float2*)(O + (size_t)node * 64 + c) = o2;
    }
}

// ---------------- host launch -------------------------------------------------
extern "C" void kernel_launch(void* const* d_in, const int* in_sizes, int n_in,
                              void* d_out, int out_size) {
    const float* x  = (const float*)d_in[0];
    const int*   ei = (const int*)d_in[1];
    const float* ew = (const float*)d_in[2];
    const float* W1 = (const float*)d_in[3];
    const float* b1 = (const float*)d_in[4];
    const float* g1 = (const float*)d_in[5];
    const float* t1 = (const float*)d_in[6];
    const float* W2 = (const float*)d_in[7];
    const float* b2 = (const float*)d_in[8];
    const float* g2 = (const float*)d_in[9];
    const float* t2 = (const float*)d_in[10];
    const float* W3 = (const float*)d_in[11];
    const float* b3 = (const float*)d_in[12];
    const float* g3 = (const float*)d_in[13];
    const float* t3 = (const float*)d_in[14];
    const int* src = ei;
    const int* dst = ei + NEDGES;

    __half *x16, *h16, *feat16, *w16_1, *w16_2, *w16_3;
    cudaGetSymbolAddress((void**)&x16, g_x16);
    cudaGetSymbolAddress((void**)&h16, g_h16);
    cudaGetSymbolAddress((void**)&feat16, g_feat16);
    cudaGetSymbolAddress((void**)&w16_1, g_w16_1);
    cudaGetSymbolAddress((void**)&w16_2, g_w16_2);
    cudaGetSymbolAddress((void**)&w16_3, g_w16_3);

    const int TB = 256;
    const int nblk_N = (NNODES + TB - 1) / TB;
    const int nblk_E = (NEDGES + TB - 1) / TB;
    const int nblk_row = (NNODES * 32 + TB - 1) / TB;    // warp per node
    const int nblk_gemm = (NNODES + 63) / 64;

    // conversions + precompute
    cvt_x_kernel<<<(NNODES * 32 + TB - 1) / TB, TB>>>(x);
    cvt_w_kernel<<<(40960 + TB - 1) / TB, TB>>>(W1, W2, W3);
    init_counts_kernel<<<nblk_N, TB>>>();
    count_kernel<<<nblk_E, TB>>>(dst, ew);
    scan_block_kernel<<<SCAN_NB, SCAN_BS>>>();
    scan_tops_kernel<<<1, 128>>>();
    scan_add_kernel<<<SCAN_NB, SCAN_BS>>>();
    fill_kernel<<<nblk_E, TB>>>(src, dst, ew);

    // layer 1
    gemm_wmma_kernel<128><<<nblk_gemm, 256>>>(x16, w16_1, h16);
    agg_ln_kernel<128, true, true><<<nblk_row, TB>>>(h16, b1, g1, t1, feat16);

    // layer 2
    gemm_wmma_kernel<128><<<nblk_gemm, 256>>>(feat16, w16_2, h16);
    agg_ln_kernel<128, true, true><<<nblk_row, TB>>>(h16, b2, g2, t2, feat16);

    // layer 3 (dout = 64, no relu), fp32 output straight to d_out
    gemm_wmma_kernel<64><<<nblk_gemm, 256>>>(feat16, w16_3, h16);
    agg_ln_kernel<64, false, false><<<nblk_row, TB>>>(h16, b3, g3, t3, d_out);
}